// round 13
// baseline (speedup 1.0000x reference)
#include <cuda_runtime.h>

#define NNODES 3000
#define BATCH  16
#define FEAT   43
#define NREL   3
#define NBUCKET (NREL*NNODES)
#define ROWS   (BATCH*NNODES)     // 48000
#define GBN    2                  // nodes per block in RGCN kernel (4 CTAs/SM)
#define OBSTR  129                // padded stride for obs staging (bank-conflict free)
#define CNTBLK 750                // count-role blocks in fused kernel (96000/128)
#define RW     (BATCH*FEAT)       // 688 floats per node-row in [n][b][f] global layout
#define RW2    (RW/2)             // 344 float2 per row
#define RW4    (RW/4)             // 172 float4 per row
#define W44    44                 // padded smem row stride (f-pad to 44)
#define MATS   (FEAT*W44)         // 1892 floats per weight matrix [f][44]
#define XROW   (BATCH*W44)        // 704 floats per padded node row in smem

// ---------------- scratch (static __device__, no allocation) ----------------
// feature tensors in [n][b][f] layout: elem(n,b,f) = n*RW + b*FEAT + f
__device__ __align__(16) float d_x [NNODES*RW];
__device__ __align__(16) float d_h1[NNODES*RW];
__device__ __align__(16) float d_h2[NNODES*RW];
__device__ int   dc_cnt[NBUCKET];
__device__ int   dc_off[NBUCKET+1];
__device__ int   dc_cur[NBUCKET];
__device__ float dc_inv[NBUCKET];
__device__ int   dc_src[96000];

// ---------------- scan (shuffle; self-zeros dc_cnt for next graph replay) ----------------
__global__ void k_scan(int E) {
    __shared__ int ws[32];
    int tid = threadIdx.x;
    int lane = tid & 31, warp = tid >> 5;
    int c[9]; int s = 0;
    #pragma unroll
    for (int i = 0; i < 9; i++) {
        int g = tid*9 + i;
        if (g < NBUCKET) { c[i] = dc_cnt[g]; dc_cnt[g] = 0; }
        else c[i] = 0;
        s += c[i];
    }
    int si = s;
    #pragma unroll
    for (int d = 1; d < 32; d <<= 1) {
        int v = __shfl_up_sync(0xffffffffu, si, d);
        if (lane >= d) si += v;
    }
    if (lane == 31) ws[warp] = si;
    __syncthreads();
    if (warp == 0) {
        int w = ws[lane];
        #pragma unroll
        for (int d = 1; d < 32; d <<= 1) {
            int v = __shfl_up_sync(0xffffffffu, w, d);
            if (lane >= d) w += v;
        }
        ws[lane] = w;
    }
    __syncthreads();
    int run = si - s + (warp > 0 ? ws[warp-1] : 0);
    #pragma unroll
    for (int i = 0; i < 9; i++) {
        int g = tid*9 + i;
        if (g < NBUCKET) {
            dc_off[g] = run;
            dc_cur[g] = run;
            dc_inv[g] = 1.0f / (float)(c[i] > 1 ? c[i] : 1);
            run += c[i];
        }
    }
    if (tid == 0) dc_off[NBUCKET] = E;
}

__global__ void k_fill(const int* __restrict__ ei, const int* __restrict__ et, int E) {
    int e = blockIdx.x*blockDim.x + threadIdx.x;
    if (e >= E) return;
    int g = et[e]*NNODES + ei[E+e];
    int p = atomicAdd(&dc_cur[g], 1);
    dc_src[p] = ei[e];
}

// ---------------- fused count + temporal (independent roles, disjoint blocks) ----------------
__global__ void __launch_bounds__(128) k_count_temporal(
    const int* __restrict__ ei, const int* __restrict__ et, int E,
    const float* __restrict__ obs,
    const float* __restrict__ ws1, const float* __restrict__ bs1,
    const float* __restrict__ ws2, const float* __restrict__ bs2,
    const float* __restrict__ wm1, const float* __restrict__ bm1,
    const float* __restrict__ wm2, const float* __restrict__ bm2)
{
    if (blockIdx.x < CNTBLK) {
        int e = blockIdx.x*128 + threadIdx.x;
        if (e < E) atomicAdd(&dc_cnt[et[e]*NNODES + ei[E+e]], 1);
        return;
    }
    // ---- temporal role (proven body; output in [n][b][f]) ----
    extern __shared__ float sm[];
    float* s_ob   = sm;                 // 150*129 = 19350
    float* s_ws2t = sm + 19350;         // 2880  [t][c][o]
    float* s_wm2t = sm + 19350 + 2880;  // 1800  [t][c][o]
    float* s_wm1  = s_wm2t + 1800;      // 189
    float* s_ws1  = s_wm1  + 189;       // 27
    float* s_bs1  = s_ws1  + 27;        // 3
    float* s_bm1  = s_bs1  + 3;         // 3
    float* s_bs2  = s_bm1  + 3;         // 20
    float* s_bm2  = s_bs2  + 20;        // 20
    int tid = threadIdx.x;

    for (int i = tid; i < 2880; i += 128) {
        int o = i/144, c = (i/48)%3, t = i%48;        // ws2 (20,3,1,48)
        s_ws2t[(t*3+c)*20 + o] = __ldg(&ws2[i]);
    }
    for (int i = tid; i < 1800; i += 128) {
        int o = i/90, c = (i/30)%3, t = i%30;         // wm2 (20,3,1,30)
        s_wm2t[(t*3+c)*20 + o] = __ldg(&wm2[i]);
    }
    for (int i = tid; i < 189; i += 128) s_wm1[i] = __ldg(&wm1[i]);
    if (tid < 27) s_ws1[tid] = __ldg(&ws1[tid]);
    if (tid < 3)  { s_bs1[tid] = __ldg(&bs1[tid]); s_bm1[tid] = __ldg(&bm1[tid]); }
    if (tid < 20) { s_bs2[tid] = __ldg(&bs2[tid]); s_bm2[tid] = __ldg(&bm2[tid]); }

    int idx0 = (blockIdx.x - CNTBLK)*128;
    for (int i = tid; i < 128*150; i += 128) {
        int slot = i/150, rem = i%150, c = rem/50, t = rem%50;
        int g = idx0 + slot; int b = g/NNODES, n = g%NNODES;
        s_ob[(c*50+t)*OBSTR + slot] = __ldg(&obs[(((size_t)(b*3+c))*NNODES + n)*50 + t]);
    }
    __syncthreads();

    const float* myob = s_ob + tid;
    int gme = idx0 + tid;
    int bb = gme / NNODES, nn = gme % NNODES;
    float* xo = d_x + (size_t)nn*RW + bb*FEAT;     // [n][b][f]

    // ---- long path ----
    for (int c = 0; c < 3; c++) {
        float m = myob[(c*50)*OBSTR];
        for (int t = 1; t < 50; t++) m = fmaxf(m, myob[(c*50+t)*OBSTR]);
        xo[40+c] = fmaxf(m, 0.f);
    }

    // ---- short path ----
    {
        float acc[20];
        #pragma unroll
        for (int o = 0; o < 20; o++) acc[o] = s_bs2[o];
        float x0[3], x1[3];
        #pragma unroll
        for (int c = 0; c < 3; c++) { x0[c] = myob[(c*50+0)*OBSTR]; x1[c] = myob[(c*50+1)*OBSTR]; }
        for (int t = 0; t < 48; t++) {
            float x2[3];
            #pragma unroll
            for (int c = 0; c < 3; c++) x2[c] = myob[(c*50+t+2)*OBSTR];
            float s1[3];
            #pragma unroll
            for (int co = 0; co < 3; co++) {
                float v = s_bs1[co];
                #pragma unroll
                for (int ci = 0; ci < 3; ci++)
                    v += x0[ci]*s_ws1[(co*3+ci)*3+0] + x1[ci]*s_ws1[(co*3+ci)*3+1] + x2[ci]*s_ws1[(co*3+ci)*3+2];
                s1[co] = fmaxf(v, 0.f);
            }
            const float* wt = s_ws2t + t*60;
            #pragma unroll
            for (int c = 0; c < 3; c++) {
                float v = s1[c];
                const float* w = wt + c*20;
                #pragma unroll
                for (int o = 0; o < 20; o++) acc[o] += v*w[o];
            }
            #pragma unroll
            for (int c = 0; c < 3; c++) { x0[c] = x1[c]; x1[c] = x2[c]; }
        }
        #pragma unroll
        for (int o = 0; o < 20; o++) xo[o] = fmaxf(acc[o], 0.f);
    }

    // ---- mid path ----
    {
        float accm[20];
        #pragma unroll
        for (int o = 0; o < 20; o++) accm[o] = s_bm2[o];
        for (int pass = 0; pass < 2; pass++) {
            float m1[3][15];
            #pragma unroll
            for (int co = 0; co < 3; co++)
                #pragma unroll
                for (int tt = 0; tt < 15; tt++) m1[co][tt] = s_bm1[co];
            for (int ci = 0; ci < 3; ci++) {
                for (int k = 0; k < 21; k++) {
                    float w0 = s_wm1[(0*3+ci)*21+k];
                    float w1 = s_wm1[(1*3+ci)*21+k];
                    float w2 = s_wm1[(2*3+ci)*21+k];
                    const float* pb = myob + (ci*50 + pass*15 + k)*OBSTR;
                    #pragma unroll
                    for (int tt = 0; tt < 15; tt++) {
                        float ov = pb[tt*OBSTR];
                        m1[0][tt] += ov*w0; m1[1][tt] += ov*w1; m1[2][tt] += ov*w2;
                    }
                }
            }
            #pragma unroll
            for (int tt = 0; tt < 15; tt++) {
                const float* wt = s_wm2t + (pass*15+tt)*60;
                #pragma unroll
                for (int c = 0; c < 3; c++) {
                    float v = fmaxf(m1[c][tt], 0.f);
                    const float* w = wt + c*20;
                    #pragma unroll
                    for (int o = 0; o < 20; o++) accm[o] += v*w[o];
                }
            }
        }
        #pragma unroll
        for (int o = 0; o < 20; o++) xo[20+o] = fmaxf(accm[o], 0.f);
    }
}

// ---------------- RGCN layer: padded-44 smem rows, float2 matmul ----------------
__global__ void __launch_bounds__(256) k_rgcn(int layer,
                       const float* __restrict__ root,
                       const float* __restrict__ rel,
                       const float* __restrict__ bias)
{
    extern __shared__ float sm[];
    float* w_s    = sm;                    // 4*MATS = 7568: [mat][f][44]
    float* bias_s = sm + 7568;             // 48 (zeros beyond 43)
    float* s_x    = sm + 7568 + 48;        // GBN*XROW = 1408 (padded rows)
    float* agg_s  = s_x + GBN*XROW;        // [r][nl][b][44] = 3*2*704 = 4224

    const float* xin  = (layer == 0) ? d_x  : d_h1;
    float*       xout = (layer == 0) ? d_h1 : d_h2;

    int tid = threadIdx.x;
    // stage weights into padded [f][44] rows (pad cols read only by junk lanes)
    for (int i = tid; i < 1849; i += 256) {
        int f = i/FEAT, o = i - f*FEAT;
        w_s[f*W44 + o] = __ldg(root + i);
    }
    for (int i = tid; i < 3*1849; i += 256) {
        int m = i/1849, rem = i - m*1849;
        int f = rem/FEAT, o = rem - f*FEAT;
        w_s[(m+1)*MATS + f*W44 + o] = __ldg(rel + i);
    }
    if (tid < 48) bias_s[tid] = (tid < FEAT) ? bias[tid] : 0.f;

    int node0 = blockIdx.x * GBN;

    // stage this block's own rows into padded layout (coalesced global reads)
    for (int i = tid; i < GBN*RW; i += 256) {
        int n = i/RW, rem = i - n*RW;
        int b = rem/FEAT, f = rem - b*FEAT;
        s_x[n*XROW + b*W44 + f] = __ldg(xin + (size_t)node0*RW + i);
    }

    // gather slot -> padded smem offsets (slot covers global floats 2s, 2s+1 of a row)
    int sA = 2*tid;
    int bA0 = sA/FEAT,     fA0 = sA     - bA0*FEAT;
    int bA1 = (sA+1)/FEAT, fA1 = (sA+1) - bA1*FEAT;
    int offA0 = bA0*W44 + fA0, offA1 = bA1*W44 + fA1;
    bool actB = tid < (RW2 - 256);   // tid < 88
    int sB = 2*(256 + tid);
    int sBc = actB ? sB : 0;
    int bB0 = sBc/FEAT,     fB0 = sBc     - bB0*FEAT;
    int bB1 = (sBc+1)/FEAT, fB1 = (sBc+1) - bB1*FEAT;
    int offB0 = bB0*W44 + fB0, offB1 = bB1*W44 + fB1;

    // ---- gather: float2 global reads (unpadded rows); all 256 threads active ----
    const float2* xin2 = (const float2*)xin;
    #pragma unroll
    for (int nl = 0; nl < GBN; nl++) {
        int n = node0 + nl;
        #pragma unroll
        for (int r = 0; r < NREL; r++) {
            int g  = r*NNODES + n;
            int s_ = dc_off[g], e_ = dc_off[g+1];
            float ax = 0.f, ay = 0.f, bx = 0.f, by = 0.f;
            int e = s_;
            for (; e + 2 <= e_; e += 2) {
                int s0 = __ldg(&dc_src[e])   * RW2;
                int s1 = __ldg(&dc_src[e+1]) * RW2;
                float2 v0 = __ldg(xin2 + s0 + tid);
                float2 v1 = __ldg(xin2 + s1 + tid);
                ax += v0.x + v1.x; ay += v0.y + v1.y;
                if (actB) {
                    float2 u0 = __ldg(xin2 + s0 + 256 + tid);
                    float2 u1 = __ldg(xin2 + s1 + 256 + tid);
                    bx += u0.x + u1.x; by += u0.y + u1.y;
                }
            }
            if (e < e_) {
                int s0 = __ldg(&dc_src[e]) * RW2;
                float2 v0 = __ldg(xin2 + s0 + tid);
                ax += v0.x; ay += v0.y;
                if (actB) {
                    float2 u0 = __ldg(xin2 + s0 + 256 + tid);
                    bx += u0.x; by += u0.y;
                }
            }
            float inv = dc_inv[g];
            float* ab = agg_s + (r*GBN + nl)*XROW;
            ab[offA0] = ax*inv;
            ab[offA1] = ay*inv;
            if (actB) { ab[offB0] = bx*inv; ab[offB1] = by*inv; }
        }
    }
    __syncthreads();

    // ---- matmul: thread -> (part, nl, b); float2 weights + f-pair unroll ----
    int b    = tid & 15;
    int nl   = (tid >> 4) & 1;
    int part = tid >> 5;          // 0..7 (warp-uniform => w reads broadcast)
    int n    = node0 + nl;
    int o0   = part * 6;          // even => float2-aligned

    float outv[6];
    #pragma unroll
    for (int oo = 0; oo < 6; oo++) outv[oo] = bias_s[o0 + oo];

    #pragma unroll
    for (int m = 0; m < 4; m++) {
        const float* ar = (m == 0) ? (s_x + nl*XROW + b*W44)
                                   : (agg_s + ((m-1)*GBN + nl)*XROW + b*W44);
        const float2* ar2 = (const float2*)ar;
        const float* wm = w_s + m*MATS + o0;
        for (int f = 0; f < 42; f += 2) {
            float2 av = ar2[f >> 1];
            const float2* w0 = (const float2*)(wm + f*W44);
            const float2* w1 = (const float2*)(wm + (f+1)*W44);
            float2 a0 = w0[0], a1 = w0[1], a2 = w0[2];
            float2 b0 = w1[0], b1 = w1[1], b2 = w1[2];
            outv[0] += av.x*a0.x + av.y*b0.x;
            outv[1] += av.x*a0.y + av.y*b0.y;
            outv[2] += av.x*a1.x + av.y*b1.x;
            outv[3] += av.x*a1.y + av.y*b1.y;
            outv[4] += av.x*a2.x + av.y*b2.x;
            outv[5] += av.x*a2.y + av.y*b2.y;
        }
        {   // f = 42
            float av = ar[42];
            const float2* wl = (const float2*)(wm + 42*W44);
            float2 l0 = wl[0], l1 = wl[1], l2 = wl[2];
            outv[0] += av*l0.x; outv[1] += av*l0.y; outv[2] += av*l1.x;
            outv[3] += av*l1.y; outv[4] += av*l2.x; outv[5] += av*l2.y;
        }
    }

    float* yo = xout + (size_t)n*RW + b*FEAT;
    #pragma unroll
    for (int oo = 0; oo < 6; oo++) {
        int o = o0 + oo;
        if (o < FEAT) {
            float v = outv[oo];
            yo[o] = v > 0.f ? v : 0.01f*v;     // leaky_relu 0.01
        }
    }
}

// ---------------- head ([n][b][f] layout) ----------------
__global__ void k_head(const float* __restrict__ la, const int* __restrict__ sel,
                       const float* __restrict__ wf, const float* __restrict__ bf,
                       float* __restrict__ out)
{
    __shared__ float sh[501];
    __shared__ float rbuf[16];
    int b = blockIdx.x, t = threadIdx.x;
    if (t == 0) sh[0] = 0.f;                 // cash logit
    if (t < 500) {
        int node = __ldg(&sel[t]);
        float v = __ldg(bf) + __ldg(wf)*__ldg(&la[b*501 + 1 + t]);
        const float* xr = d_x  + (size_t)node*RW + b*FEAT;
        const float* hr = d_h2 + (size_t)node*RW + b*FEAT;
        #pragma unroll
        for (int f = 0; f < FEAT; f++) v += __ldg(&wf[1 + f])  * __ldg(xr + f);
        #pragma unroll
        for (int f = 0; f < FEAT; f++) v += __ldg(&wf[44 + f]) * __ldg(hr + f);
        sh[1 + t] = v;
    }
    __syncthreads();

    float m = -1e30f;
    for (int i = t; i < 501; i += 512) m = fmaxf(m, sh[i]);
    #pragma unroll
    for (int off = 16; off; off >>= 1) m = fmaxf(m, __shfl_xor_sync(0xffffffffu, m, off));
    if ((t & 31) == 0) rbuf[t >> 5] = m;
    __syncthreads();
    if (t == 0) { float mm = rbuf[0]; for (int w = 1; w < 16; w++) mm = fmaxf(mm, rbuf[w]); rbuf[0] = mm; }
    __syncthreads();
    float gm = rbuf[0];
    __syncthreads();

    float ssum = 0.f;
    for (int i = t; i < 501; i += 512) { float e = __expf(sh[i] - gm); sh[i] = e; ssum += e; }
    #pragma unroll
    for (int off = 16; off; off >>= 1) ssum += __shfl_xor_sync(0xffffffffu, ssum, off);
    if ((t & 31) == 0) rbuf[t >> 5] = ssum;
    __syncthreads();
    if (t == 0) { float s2 = 0.f; for (int w = 0; w < 16; w++) s2 += rbuf[w]; rbuf[0] = s2; }
    __syncthreads();
    float invs = 1.0f / rbuf[0];
    for (int i = t; i < 501; i += 512) out[b*501 + i] = sh[i] * invs;
}

// ---------------- launch ----------------
extern "C" void kernel_launch(void* const* d_in, const int* in_sizes, int n_in,
                              void* d_out, int out_size)
{
    const float* obs   = (const float*)d_in[0];
    const float* la    = (const float*)d_in[1];
    const int*   ei    = (const int*)  d_in[2];
    const int*   et    = (const int*)  d_in[3];
    const int*   sel   = (const int*)  d_in[4];
    const float* ws1   = (const float*)d_in[5];
    const float* bs1   = (const float*)d_in[6];
    const float* ws2   = (const float*)d_in[7];
    const float* bs2   = (const float*)d_in[8];
    const float* wm1   = (const float*)d_in[9];
    const float* bm1   = (const float*)d_in[10];
    const float* wm2   = (const float*)d_in[11];
    const float* bm2   = (const float*)d_in[12];
    const float* root1 = (const float*)d_in[13];
    const float* rel1  = (const float*)d_in[14];
    const float* bias1 = (const float*)d_in[15];
    const float* root2 = (const float*)d_in[16];
    const float* rel2  = (const float*)d_in[17];
    const float* bias2 = (const float*)d_in[18];
    const float* wf    = (const float*)d_in[19];
    const float* bf    = (const float*)d_in[20];
    float* out = (float*)d_out;

    int E = in_sizes[3];   // 96000

    int smem_t = (150*OBSTR + 2880 + 1800 + 189 + 27 + 3 + 3 + 20 + 20) * (int)sizeof(float);
    int smem_r = (7568 + 48 + GBN*XROW + NREL*GBN*XROW) * (int)sizeof(float);   // 52992 B -> 4 CTAs/SM
    cudaFuncSetAttribute(k_count_temporal, cudaFuncAttributeMaxDynamicSharedMemorySize, smem_t);
    cudaFuncSetAttribute(k_rgcn,           cudaFuncAttributeMaxDynamicSharedMemorySize, smem_r);

    // #0 fused count + temporal   (dc_cnt zeroed by previous scan; BSS-zero on first call)
    k_count_temporal<<<CNTBLK + ROWS/128, 128, smem_t>>>(ei, et, E,
        obs, ws1, bs1, ws2, bs2, wm1, bm1, wm2, bm2);
    // #1 scan (+ self-zero dc_cnt)
    k_scan<<<1, 1024>>>(E);
    // #2 fill
    k_fill<<<(E + 127)/128, 128>>>(ei, et, E);
    // #3, #4 RGCN layers   (#3 is what ncu captures)
    k_rgcn<<<NNODES/GBN, 256, smem_r>>>(0, root1, rel1, bias1);
    k_rgcn<<<NNODES/GBN, 256, smem_r>>>(1, root2, rel2, bias2);
    // #5 head
    k_head<<<BATCH, 512>>>(la, sel, wf, bf, out);
}

// round 14
// speedup vs baseline: 1.0365x; 1.0365x over previous
#include <cuda_runtime.h>

#define NNODES 3000
#define BATCH  16
#define FEAT   43
#define NREL   3
#define NBUCKET (NREL*NNODES)
#define ROWS   (BATCH*NNODES)     // 48000
#define GBN    2                  // nodes per block in RGCN kernel (4 CTAs/SM)
#define OBSTR  129                // padded stride for obs staging (bank-conflict free)
#define RW     (BATCH*FEAT)       // 688 floats per node-row in [n][b][f] global layout
#define RW2    (RW/2)             // 344 float2 per row
#define RW4    (RW/4)             // 172 float4 per row

// ---------------- scratch (static __device__, no allocation) ----------------
// feature tensors in [n][b][f] layout: elem(n,b,f) = n*RW + b*FEAT + f
__device__ __align__(16) float d_x [NNODES*RW];
__device__ __align__(16) float d_h1[NNODES*RW];
__device__ __align__(16) float d_h2[NNODES*RW];
__device__ int   dc_cnt[NBUCKET];
__device__ int   dc_off[NBUCKET+1];
__device__ int   dc_cur[NBUCKET];
__device__ float dc_inv[NBUCKET];
__device__ int   dc_src[96000];

// ---------------- CSR build ----------------
__global__ void k_count(const int* __restrict__ ei, const int* __restrict__ et, int E) {
    int e = blockIdx.x*blockDim.x + threadIdx.x;
    if (e >= E) return;
    atomicAdd(&dc_cnt[et[e]*NNODES + ei[E+e]], 1);
}

// shuffle scan; self-zeros dc_cnt for next graph replay (BSS starts zero)
__global__ void k_scan(int E) {
    __shared__ int ws[32];
    int tid = threadIdx.x;
    int lane = tid & 31, warp = tid >> 5;
    int c[9]; int s = 0;
    #pragma unroll
    for (int i = 0; i < 9; i++) {
        int g = tid*9 + i;
        if (g < NBUCKET) { c[i] = dc_cnt[g]; dc_cnt[g] = 0; }
        else c[i] = 0;
        s += c[i];
    }
    int si = s;
    #pragma unroll
    for (int d = 1; d < 32; d <<= 1) {
        int v = __shfl_up_sync(0xffffffffu, si, d);
        if (lane >= d) si += v;
    }
    if (lane == 31) ws[warp] = si;
    __syncthreads();
    if (warp == 0) {
        int w = ws[lane];
        #pragma unroll
        for (int d = 1; d < 32; d <<= 1) {
            int v = __shfl_up_sync(0xffffffffu, w, d);
            if (lane >= d) w += v;
        }
        ws[lane] = w;
    }
    __syncthreads();
    int run = si - s + (warp > 0 ? ws[warp-1] : 0);
    #pragma unroll
    for (int i = 0; i < 9; i++) {
        int g = tid*9 + i;
        if (g < NBUCKET) {
            dc_off[g] = run;
            dc_cur[g] = run;
            dc_inv[g] = 1.0f / (float)(c[i] > 1 ? c[i] : 1);
            run += c[i];
        }
    }
    if (tid == 0) dc_off[NBUCKET] = E;
}

__global__ void k_fill(const int* __restrict__ ei, const int* __restrict__ et, int E) {
    int e = blockIdx.x*blockDim.x + threadIdx.x;
    if (e >= E) return;
    int g = et[e]*NNODES + ei[E+e];
    int p = atomicAdd(&dc_cur[g], 1);
    dc_src[p] = ei[e];
}

// ---------------- temporal: weights at 16B-aligned offsets, float4 broadcast reads ----------------
__global__ void __launch_bounds__(128) k_temporal(const float* __restrict__ obs,
    const float* __restrict__ ws1, const float* __restrict__ bs1,
    const float* __restrict__ ws2, const float* __restrict__ bs2,
    const float* __restrict__ wm1, const float* __restrict__ bm1,
    const float* __restrict__ wm2, const float* __restrict__ bm2)
{
    extern __shared__ float sm[];
    float* s_ws2t = sm;            // 2880  [t][c][o], rows of 20 floats (80B, 16B-aligned)
    float* s_wm2t = sm + 2880;     // 1800  [t][c][o]
    float* s_bs2  = sm + 4680;     // 20
    float* s_bm2  = sm + 4700;     // 20
    float* s_wm1  = sm + 4720;     // 189
    float* s_ws1  = sm + 4909;     // 27
    float* s_bs1  = sm + 4936;     // 3
    float* s_bm1  = sm + 4939;     // 3
    float* s_ob   = sm + 4944;     // 150*129 = 19350
    int tid = threadIdx.x;

    for (int i = tid; i < 2880; i += 128) {
        int o = i/144, c = (i/48)%3, t = i%48;        // ws2 (20,3,1,48)
        s_ws2t[(t*3+c)*20 + o] = __ldg(&ws2[i]);
    }
    for (int i = tid; i < 1800; i += 128) {
        int o = i/90, c = (i/30)%3, t = i%30;         // wm2 (20,3,1,30)
        s_wm2t[(t*3+c)*20 + o] = __ldg(&wm2[i]);
    }
    for (int i = tid; i < 189; i += 128) s_wm1[i] = __ldg(&wm1[i]);
    if (tid < 27) s_ws1[tid] = __ldg(&ws1[tid]);
    if (tid < 3)  { s_bs1[tid] = __ldg(&bs1[tid]); s_bm1[tid] = __ldg(&bm1[tid]); }
    if (tid < 20) { s_bs2[tid] = __ldg(&bs2[tid]); s_bm2[tid] = __ldg(&bm2[tid]); }

    int idx0 = blockIdx.x*128;
    for (int i = tid; i < 128*150; i += 128) {
        int slot = i/150, rem = i%150, c = rem/50, t = rem%50;
        int g = idx0 + slot; int b = g/NNODES, n = g%NNODES;
        s_ob[(c*50+t)*OBSTR + slot] = __ldg(&obs[(((size_t)(b*3+c))*NNODES + n)*50 + t]);
    }
    __syncthreads();

    const float* myob = s_ob + tid;
    int gme = idx0 + tid;
    int bb = gme / NNODES, nn = gme % NNODES;
    float* xo = d_x + (size_t)nn*RW + bb*FEAT;     // [n][b][f]

    // ---- long path ----
    for (int c = 0; c < 3; c++) {
        float m = myob[(c*50)*OBSTR];
        for (int t = 1; t < 50; t++) m = fmaxf(m, myob[(c*50+t)*OBSTR]);
        xo[40+c] = fmaxf(m, 0.f);
    }

    // ---- short path: conv(1x3,3->3)+relu -> conv(1x48,3->20)+relu ----
    {
        float acc[20];
        #pragma unroll
        for (int o = 0; o < 20; o++) acc[o] = s_bs2[o];
        float x0[3], x1[3];
        #pragma unroll
        for (int c = 0; c < 3; c++) { x0[c] = myob[(c*50+0)*OBSTR]; x1[c] = myob[(c*50+1)*OBSTR]; }
        for (int t = 0; t < 48; t++) {
            float x2[3];
            #pragma unroll
            for (int c = 0; c < 3; c++) x2[c] = myob[(c*50+t+2)*OBSTR];
            float s1[3];
            #pragma unroll
            for (int co = 0; co < 3; co++) {
                float v = s_bs1[co];
                #pragma unroll
                for (int ci = 0; ci < 3; ci++)
                    v += x0[ci]*s_ws1[(co*3+ci)*3+0] + x1[ci]*s_ws1[(co*3+ci)*3+1] + x2[ci]*s_ws1[(co*3+ci)*3+2];
                s1[co] = fmaxf(v, 0.f);
            }
            const float4* wt4 = (const float4*)(s_ws2t + t*60);   // 240B-aligned
            #pragma unroll
            for (int c = 0; c < 3; c++) {
                float v = s1[c];
                #pragma unroll
                for (int q = 0; q < 5; q++) {
                    float4 w = wt4[c*5 + q];
                    acc[q*4+0] += v*w.x; acc[q*4+1] += v*w.y;
                    acc[q*4+2] += v*w.z; acc[q*4+3] += v*w.w;
                }
            }
            #pragma unroll
            for (int c = 0; c < 3; c++) { x0[c] = x1[c]; x1[c] = x2[c]; }
        }
        #pragma unroll
        for (int o = 0; o < 20; o++) xo[o] = fmaxf(acc[o], 0.f);
    }

    // ---- mid path: conv(1x21,3->3)+relu -> conv(1x30,3->20)+relu ----
    {
        float accm[20];
        #pragma unroll
        for (int o = 0; o < 20; o++) accm[o] = s_bm2[o];
        for (int pass = 0; pass < 2; pass++) {
            float m1[3][15];
            #pragma unroll
            for (int co = 0; co < 3; co++)
                #pragma unroll
                for (int tt = 0; tt < 15; tt++) m1[co][tt] = s_bm1[co];
            for (int ci = 0; ci < 3; ci++) {
                for (int k = 0; k < 21; k++) {
                    float w0 = s_wm1[(0*3+ci)*21+k];
                    float w1 = s_wm1[(1*3+ci)*21+k];
                    float w2 = s_wm1[(2*3+ci)*21+k];
                    const float* pb = myob + (ci*50 + pass*15 + k)*OBSTR;
                    #pragma unroll
                    for (int tt = 0; tt < 15; tt++) {
                        float ov = pb[tt*OBSTR];
                        m1[0][tt] += ov*w0; m1[1][tt] += ov*w1; m1[2][tt] += ov*w2;
                    }
                }
            }
            #pragma unroll
            for (int tt = 0; tt < 15; tt++) {
                const float4* wt4 = (const float4*)(s_wm2t + (pass*15+tt)*60);
                #pragma unroll
                for (int c = 0; c < 3; c++) {
                    float v = fmaxf(m1[c][tt], 0.f);
                    #pragma unroll
                    for (int q = 0; q < 5; q++) {
                        float4 w = wt4[c*5 + q];
                        accm[q*4+0] += v*w.x; accm[q*4+1] += v*w.y;
                        accm[q*4+2] += v*w.z; accm[q*4+3] += v*w.w;
                    }
                }
            }
        }
        #pragma unroll
        for (int o = 0; o < 20; o++) xo[20+o] = fmaxf(accm[o], 0.f);
    }
}

// ---------------- RGCN layer (round-12 proven version, verbatim) ----------------
__global__ void __launch_bounds__(256) k_rgcn(int layer,
                       const float* __restrict__ root,
                       const float* __restrict__ rel,
                       const float* __restrict__ bias)
{
    extern __shared__ float sm[];
    float* w_s    = sm;              // 4*1849 = 7396: [root, rel0..2], row-major [f][o]
    float* bias_s = sm + 7396;       // 48 (padded, zeros beyond 43)
    float* s_x    = sm + 7444;       // GBN*RW = 1376: block's own node rows
    float* agg_s  = sm + 7444 + GBN*RW;   // [r][nl][RW] = 3*2*688 = 4128

    const float* xin  = (layer == 0) ? d_x  : d_h1;
    float*       xout = (layer == 0) ? d_h1 : d_h2;

    int tid = threadIdx.x;
    for (int i = tid; i < 1849;   i += 256) w_s[i]       = __ldg(root + i);
    for (int i = tid; i < 3*1849; i += 256) w_s[1849+i]  = __ldg(rel + i);
    if (tid < 48) bias_s[tid] = (tid < FEAT) ? bias[tid] : 0.f;

    int node0 = blockIdx.x * GBN;

    // stage this block's own rows (root term): 2*688 contiguous floats
    {
        const float4* xr4 = (const float4*)(xin + (size_t)node0*RW);
        float4* sx4 = (float4*)s_x;
        for (int i = tid; i < GBN*RW4; i += 256) sx4[i] = __ldg(xr4 + i);
    }

    // ---- gather: float2 slots; thread owns slot tid (all 256) + slot 256+tid (tid<88) ----
    const float2* xin2 = (const float2*)xin;
    bool actB = tid < (RW2 - 256);   // tid < 88
    #pragma unroll
    for (int nl = 0; nl < GBN; nl++) {
        int n = node0 + nl;
        #pragma unroll
        for (int r = 0; r < NREL; r++) {
            int g  = r*NNODES + n;
            int s_ = dc_off[g], e_ = dc_off[g+1];
            float ax = 0.f, ay = 0.f, bx = 0.f, by = 0.f;
            int e = s_;
            for (; e + 2 <= e_; e += 2) {
                int s0 = __ldg(&dc_src[e])   * RW2;
                int s1 = __ldg(&dc_src[e+1]) * RW2;
                float2 v0 = __ldg(xin2 + s0 + tid);
                float2 v1 = __ldg(xin2 + s1 + tid);
                ax += v0.x + v1.x; ay += v0.y + v1.y;
                if (actB) {
                    float2 u0 = __ldg(xin2 + s0 + 256 + tid);
                    float2 u1 = __ldg(xin2 + s1 + 256 + tid);
                    bx += u0.x + u1.x; by += u0.y + u1.y;
                }
            }
            if (e < e_) {
                int s0 = __ldg(&dc_src[e]) * RW2;
                float2 v0 = __ldg(xin2 + s0 + tid);
                ax += v0.x; ay += v0.y;
                if (actB) {
                    float2 u0 = __ldg(xin2 + s0 + 256 + tid);
                    bx += u0.x; by += u0.y;
                }
            }
            float inv = dc_inv[g];
            float2* ab = (float2*)(agg_s + (r*GBN + nl)*RW);
            float2 wa; wa.x = ax*inv; wa.y = ay*inv;
            ab[tid] = wa;
            if (actB) { float2 wb2; wb2.x = bx*inv; wb2.y = by*inv; ab[256 + tid] = wb2; }
        }
    }
    __syncthreads();

    // ---- matmul: thread -> (part, nl, b); 8 parts of 6 outputs (o>=43 junk, never stored) ----
    int b    = tid & 15;
    int nl   = (tid >> 4) & 1;
    int part = tid >> 5;          // 0..7 (constant per warp => w_s reads broadcast)
    int n    = node0 + nl;
    int o0   = part * 6;

    float outv[6];
    #pragma unroll
    for (int oo = 0; oo < 6; oo++) outv[oo] = bias_s[o0 + oo];

    const float* xr = s_x + nl*RW + b*FEAT;
    for (int f = 0; f < FEAT; f++) {
        float xv = xr[f];
        const float* wr = w_s + f*FEAT + o0;
        #pragma unroll
        for (int oo = 0; oo < 6; oo++) outv[oo] += xv * wr[oo];
    }
    #pragma unroll
    for (int r = 0; r < NREL; r++) {
        const float* ar = agg_s + (r*GBN + nl)*RW + b*FEAT;
        const float* wb = w_s + (1 + r)*1849 + o0;
        for (int f = 0; f < FEAT; f++) {
            float av = ar[f];
            const float* wr = wb + f*FEAT;
            #pragma unroll
            for (int oo = 0; oo < 6; oo++) outv[oo] += av * wr[oo];
        }
    }

    float* yo = xout + (size_t)n*RW + b*FEAT;
    #pragma unroll
    for (int oo = 0; oo < 6; oo++) {
        int o = o0 + oo;
        if (o < FEAT) {
            float v = outv[oo];
            yo[o] = v > 0.f ? v : 0.01f*v;     // leaky_relu 0.01
        }
    }
}

// ---------------- head ([n][b][f] layout) ----------------
__global__ void k_head(const float* __restrict__ la, const int* __restrict__ sel,
                       const float* __restrict__ wf, const float* __restrict__ bf,
                       float* __restrict__ out)
{
    __shared__ float sh[501];
    __shared__ float rbuf[16];
    int b = blockIdx.x, t = threadIdx.x;
    if (t == 0) sh[0] = 0.f;                 // cash logit
    if (t < 500) {
        int node = __ldg(&sel[t]);
        float v = __ldg(bf) + __ldg(wf)*__ldg(&la[b*501 + 1 + t]);
        const float* xr = d_x  + (size_t)node*RW + b*FEAT;
        const float* hr = d_h2 + (size_t)node*RW + b*FEAT;
        #pragma unroll
        for (int f = 0; f < FEAT; f++) v += __ldg(&wf[1 + f])  * __ldg(xr + f);
        #pragma unroll
        for (int f = 0; f < FEAT; f++) v += __ldg(&wf[44 + f]) * __ldg(hr + f);
        sh[1 + t] = v;
    }
    __syncthreads();

    float m = -1e30f;
    for (int i = t; i < 501; i += 512) m = fmaxf(m, sh[i]);
    #pragma unroll
    for (int off = 16; off; off >>= 1) m = fmaxf(m, __shfl_xor_sync(0xffffffffu, m, off));
    if ((t & 31) == 0) rbuf[t >> 5] = m;
    __syncthreads();
    if (t == 0) { float mm = rbuf[0]; for (int w = 1; w < 16; w++) mm = fmaxf(mm, rbuf[w]); rbuf[0] = mm; }
    __syncthreads();
    float gm = rbuf[0];
    __syncthreads();

    float ssum = 0.f;
    for (int i = t; i < 501; i += 512) { float e = __expf(sh[i] - gm); sh[i] = e; ssum += e; }
    #pragma unroll
    for (int off = 16; off; off >>= 1) ssum += __shfl_xor_sync(0xffffffffu, ssum, off);
    if ((t & 31) == 0) rbuf[t >> 5] = ssum;
    __syncthreads();
    if (t == 0) { float s2 = 0.f; for (int w = 0; w < 16; w++) s2 += rbuf[w]; rbuf[0] = s2; }
    __syncthreads();
    float invs = 1.0f / rbuf[0];
    for (int i = t; i < 501; i += 512) out[b*501 + i] = sh[i] * invs;
}

// ---------------- launch ----------------
extern "C" void kernel_launch(void* const* d_in, const int* in_sizes, int n_in,
                              void* d_out, int out_size)
{
    const float* obs   = (const float*)d_in[0];
    const float* la    = (const float*)d_in[1];
    const int*   ei    = (const int*)  d_in[2];
    const int*   et    = (const int*)  d_in[3];
    const int*   sel   = (const int*)  d_in[4];
    const float* ws1   = (const float*)d_in[5];
    const float* bs1   = (const float*)d_in[6];
    const float* ws2   = (const float*)d_in[7];
    const float* bs2   = (const float*)d_in[8];
    const float* wm1   = (const float*)d_in[9];
    const float* bm1   = (const float*)d_in[10];
    const float* wm2   = (const float*)d_in[11];
    const float* bm2   = (const float*)d_in[12];
    const float* root1 = (const float*)d_in[13];
    const float* rel1  = (const float*)d_in[14];
    const float* bias1 = (const float*)d_in[15];
    const float* root2 = (const float*)d_in[16];
    const float* rel2  = (const float*)d_in[17];
    const float* bias2 = (const float*)d_in[18];
    const float* wf    = (const float*)d_in[19];
    const float* bf    = (const float*)d_in[20];
    float* out = (float*)d_out;

    int E = in_sizes[3];   // 96000

    int smem_t = (4944 + 150*OBSTR) * (int)sizeof(float);                      // 97176 B
    int smem_r = (7444 + GBN*RW + NREL*GBN*RW) * (int)sizeof(float);           // 51792 B -> 4 CTAs/SM
    cudaFuncSetAttribute(k_temporal, cudaFuncAttributeMaxDynamicSharedMemorySize, smem_t);
    cudaFuncSetAttribute(k_rgcn,     cudaFuncAttributeMaxDynamicSharedMemorySize, smem_r);

    // #0 count (dc_cnt zeroed by previous scan; BSS-zero on first call)
    k_count<<<(E + 255)/256, 256>>>(ei, et, E);
    // #1 scan (+ self-zero dc_cnt)
    k_scan<<<1, 1024>>>(E);
    // #2 fill
    k_fill<<<(E + 127)/128, 128>>>(ei, et, E);
    // #3 temporal   (ncu captures launch #3)
    k_temporal<<<ROWS/128, 128, smem_t>>>(obs, ws1, bs1, ws2, bs2, wm1, bm1, wm2, bm2);
    // #4, #5 RGCN layers
    k_rgcn<<<NNODES/GBN, 256, smem_r>>>(0, root1, rel1, bias1);
    k_rgcn<<<NNODES/GBN, 256, smem_r>>>(1, root2, rel2, bias2);
    // #6 head
    k_head<<<BATCH, 512>>>(la, sel, wf, bf, out);
}

// round 16
// speedup vs baseline: 1.1424x; 1.1021x over previous
#include <cuda_runtime.h>

#define NNODES 3000
#define BATCH  16
#define FEAT   43
#define NREL   3
#define NBUCKET (NREL*NNODES)
#define ROWS   (BATCH*NNODES)     // 48000
#define GBN    2                  // nodes per block in RGCN kernel (4 CTAs/SM)
#define OBSTR  129                // padded stride for obs staging (bank-conflict free)
#define RW     (BATCH*FEAT)       // 688 floats per node-row in [n][b][f] global layout
#define RW2    (RW/2)             // 344 float2 per row
#define RW4    (RW/4)             // 172 float4 per row

// ---------------- scratch (static __device__, no allocation) ----------------
// feature tensors in [n][b][f] layout: elem(n,b,f) = n*RW + b*FEAT + f
__device__ __align__(16) float d_x [NNODES*RW];
__device__ __align__(16) float d_h1[NNODES*RW];
__device__ __align__(16) float d_h2[NNODES*RW];
__device__ int   dc_cnt[NBUCKET];
__device__ int   dc_off[NBUCKET+1];
__device__ int   dc_cur[NBUCKET];
__device__ float dc_inv[NBUCKET];
__device__ int   dc_src[96000];

// ---------------- CSR build ----------------
__global__ void k_count(const int* __restrict__ ei, const int* __restrict__ et, int E) {
    int e = blockIdx.x*blockDim.x + threadIdx.x;
    if (e >= E) return;
    atomicAdd(&dc_cnt[et[e]*NNODES + ei[E+e]], 1);
}

// shuffle scan; self-zeros dc_cnt for next graph replay (BSS starts zero)
__global__ void k_scan(int E) {
    __shared__ int ws[32];
    int tid = threadIdx.x;
    int lane = tid & 31, warp = tid >> 5;
    int c[9]; int s = 0;
    #pragma unroll
    for (int i = 0; i < 9; i++) {
        int g = tid*9 + i;
        if (g < NBUCKET) { c[i] = dc_cnt[g]; dc_cnt[g] = 0; }
        else c[i] = 0;
        s += c[i];
    }
    int si = s;
    #pragma unroll
    for (int d = 1; d < 32; d <<= 1) {
        int v = __shfl_up_sync(0xffffffffu, si, d);
        if (lane >= d) si += v;
    }
    if (lane == 31) ws[warp] = si;
    __syncthreads();
    if (warp == 0) {
        int w = ws[lane];
        #pragma unroll
        for (int d = 1; d < 32; d <<= 1) {
            int v = __shfl_up_sync(0xffffffffu, w, d);
            if (lane >= d) w += v;
        }
        ws[lane] = w;
    }
    __syncthreads();
    int run = si - s + (warp > 0 ? ws[warp-1] : 0);
    #pragma unroll
    for (int i = 0; i < 9; i++) {
        int g = tid*9 + i;
        if (g < NBUCKET) {
            dc_off[g] = run;
            dc_cur[g] = run;
            dc_inv[g] = 1.0f / (float)(c[i] > 1 ? c[i] : 1);
            run += c[i];
        }
    }
    if (tid == 0) dc_off[NBUCKET] = E;
}

__global__ void k_fill(const int* __restrict__ ei, const int* __restrict__ et, int E) {
    int e = blockIdx.x*blockDim.x + threadIdx.x;
    if (e >= E) return;
    int g = et[e]*NNODES + ei[E+e];
    int p = atomicAdd(&dc_cur[g], 1);
    dc_src[p] = ei[e];
}

// ---------------- temporal: 384 threads, 3 warp-roles share one 128-slot obs stage ----------------
// role 0 (warps 0-3):  long + short paths
// role 1 (warps 4-7):  mid-conv pass 0 (t=0..14), combines + writes
// role 2 (warps 8-11): mid-conv pass 1 (t=15..29), writes partial to s_part
__global__ void __launch_bounds__(384, 2) k_temporal(const float* __restrict__ obs,
    const float* __restrict__ ws1, const float* __restrict__ bs1,
    const float* __restrict__ ws2, const float* __restrict__ bs2,
    const float* __restrict__ wm1, const float* __restrict__ bm1,
    const float* __restrict__ wm2, const float* __restrict__ bm2)
{
    extern __shared__ float sm[];
    float* s_ws2t = sm;            // 2880  [t][c][o] rows of 20 (16B-aligned)
    float* s_wm2t = sm + 2880;     // 1800  [t][c][o]
    float* s_bs2  = sm + 4680;     // 20
    float* s_bm2  = sm + 4700;     // 20
    float* s_wm1  = sm + 4720;     // 189
    float* s_ws1  = sm + 4909;     // 27
    float* s_bs1  = sm + 4936;     // 3
    float* s_bm1  = sm + 4939;     // 3 (+2 pad)
    float* s_part = sm + 4944;     // 20*128 = 2560, [o][slot]
    float* s_ob   = sm + 7504;     // 150*129 = 19350
    int tid = threadIdx.x;

    for (int i = tid; i < 2880; i += 384) {
        int o = i/144, c = (i/48)%3, t = i%48;        // ws2 (20,3,1,48)
        s_ws2t[(t*3+c)*20 + o] = __ldg(&ws2[i]);
    }
    for (int i = tid; i < 1800; i += 384) {
        int o = i/90, c = (i/30)%3, t = i%30;         // wm2 (20,3,1,30)
        s_wm2t[(t*3+c)*20 + o] = __ldg(&wm2[i]);
    }
    for (int i = tid; i < 189; i += 384) s_wm1[i] = __ldg(&wm1[i]);
    if (tid < 27) s_ws1[tid] = __ldg(&ws1[tid]);
    if (tid < 3)  { s_bs1[tid] = __ldg(&bs1[tid]); s_bm1[tid] = __ldg(&bm1[tid]); }
    if (tid < 20) { s_bs2[tid] = __ldg(&bs2[tid]); s_bm2[tid] = __ldg(&bm2[tid]); }

    int idx0 = blockIdx.x*128;
    for (int i = tid; i < 128*150; i += 384) {
        int slot = i/150, rem = i%150, c = rem/50, t = rem%50;
        int g = idx0 + slot; int b = g/NNODES, n = g%NNODES;
        s_ob[(c*50+t)*OBSTR + slot] = __ldg(&obs[(((size_t)(b*3+c))*NNODES + n)*50 + t]);
    }
    __syncthreads();

    int role = tid >> 7;           // 0,1,2 (warp-uniform)
    int slot = tid & 127;
    const float* myob = s_ob + slot;
    int gme = idx0 + slot;
    int bb = gme / NNODES, nn = gme % NNODES;
    float* xo = d_x + (size_t)nn*RW + bb*FEAT;     // [n][b][f]

    if (role == 0) {
        // ---- long path ----
        #pragma unroll
        for (int c = 0; c < 3; c++) {
            float m = myob[(c*50)*OBSTR];
            for (int t = 1; t < 50; t++) m = fmaxf(m, myob[(c*50+t)*OBSTR]);
            xo[40+c] = fmaxf(m, 0.f);
        }
        // ---- short path: conv(1x3,3->3)+relu -> conv(1x48,3->20)+relu ----
        float acc[20];
        #pragma unroll
        for (int o = 0; o < 20; o++) acc[o] = s_bs2[o];
        float x0[3], x1[3];
        #pragma unroll
        for (int c = 0; c < 3; c++) { x0[c] = myob[(c*50+0)*OBSTR]; x1[c] = myob[(c*50+1)*OBSTR]; }
        for (int t = 0; t < 48; t++) {
            float x2[3];
            #pragma unroll
            for (int c = 0; c < 3; c++) x2[c] = myob[(c*50+t+2)*OBSTR];
            float s1[3];
            #pragma unroll
            for (int co = 0; co < 3; co++) {
                float v = s_bs1[co];
                #pragma unroll
                for (int ci = 0; ci < 3; ci++)
                    v += x0[ci]*s_ws1[(co*3+ci)*3+0] + x1[ci]*s_ws1[(co*3+ci)*3+1] + x2[ci]*s_ws1[(co*3+ci)*3+2];
                s1[co] = fmaxf(v, 0.f);
            }
            const float4* wt4 = (const float4*)(s_ws2t + t*60);
            #pragma unroll
            for (int c = 0; c < 3; c++) {
                float v = s1[c];
                #pragma unroll
                for (int q = 0; q < 5; q++) {
                    float4 w = wt4[c*5 + q];
                    acc[q*4+0] += v*w.x; acc[q*4+1] += v*w.y;
                    acc[q*4+2] += v*w.z; acc[q*4+3] += v*w.w;
                }
            }
            #pragma unroll
            for (int c = 0; c < 3; c++) { x0[c] = x1[c]; x1[c] = x2[c]; }
        }
        #pragma unroll
        for (int o = 0; o < 20; o++) xo[o] = fmaxf(acc[o], 0.f);
    }

    float accm[20];
    if (role >= 1) {
        // ---- mid path pass (role-1): conv(1x21,3->3)+relu -> conv(1x30,3->20) partial ----
        int pass = role - 1;
        #pragma unroll
        for (int o = 0; o < 20; o++) accm[o] = (pass == 0) ? s_bm2[o] : 0.f;
        float m1[3][15];
        #pragma unroll
        for (int co = 0; co < 3; co++)
            #pragma unroll
            for (int tt = 0; tt < 15; tt++) m1[co][tt] = s_bm1[co];
        for (int ci = 0; ci < 3; ci++) {
            for (int k = 0; k < 21; k++) {
                float w0 = s_wm1[(0*3+ci)*21+k];
                float w1 = s_wm1[(1*3+ci)*21+k];
                float w2 = s_wm1[(2*3+ci)*21+k];
                const float* pb = myob + (ci*50 + pass*15 + k)*OBSTR;
                #pragma unroll
                for (int tt = 0; tt < 15; tt++) {
                    float ov = pb[tt*OBSTR];
                    m1[0][tt] += ov*w0; m1[1][tt] += ov*w1; m1[2][tt] += ov*w2;
                }
            }
        }
        #pragma unroll
        for (int tt = 0; tt < 15; tt++) {
            const float4* wt4 = (const float4*)(s_wm2t + (pass*15+tt)*60);
            #pragma unroll
            for (int c = 0; c < 3; c++) {
                float v = fmaxf(m1[c][tt], 0.f);
                #pragma unroll
                for (int q = 0; q < 5; q++) {
                    float4 w = wt4[c*5 + q];
                    accm[q*4+0] += v*w.x; accm[q*4+1] += v*w.y;
                    accm[q*4+2] += v*w.z; accm[q*4+3] += v*w.w;
                }
            }
        }
        if (role == 2) {
            #pragma unroll
            for (int o = 0; o < 20; o++) s_part[o*128 + slot] = accm[o];
        }
    }
    __syncthreads();
    if (role == 1) {
        #pragma unroll
        for (int o = 0; o < 20; o++) {
            float v = accm[o] + s_part[o*128 + slot];
            xo[20+o] = fmaxf(v, 0.f);
        }
    }
}

// ---------------- RGCN layer (round-12 proven version, verbatim) ----------------
__global__ void __launch_bounds__(256) k_rgcn(int layer,
                       const float* __restrict__ root,
                       const float* __restrict__ rel,
                       const float* __restrict__ bias)
{
    extern __shared__ float sm[];
    float* w_s    = sm;              // 4*1849 = 7396: [root, rel0..2], row-major [f][o]
    float* bias_s = sm + 7396;       // 48 (padded, zeros beyond 43)
    float* s_x    = sm + 7444;       // GBN*RW = 1376: block's own node rows
    float* agg_s  = sm + 7444 + GBN*RW;   // [r][nl][RW] = 3*2*688 = 4128

    const float* xin  = (layer == 0) ? d_x  : d_h1;
    float*       xout = (layer == 0) ? d_h1 : d_h2;

    int tid = threadIdx.x;
    for (int i = tid; i < 1849;   i += 256) w_s[i]       = __ldg(root + i);
    for (int i = tid; i < 3*1849; i += 256) w_s[1849+i]  = __ldg(rel + i);
    if (tid < 48) bias_s[tid] = (tid < FEAT) ? bias[tid] : 0.f;

    int node0 = blockIdx.x * GBN;

    // stage this block's own rows (root term): 2*688 contiguous floats
    {
        const float4* xr4 = (const float4*)(xin + (size_t)node0*RW);
        float4* sx4 = (float4*)s_x;
        for (int i = tid; i < GBN*RW4; i += 256) sx4[i] = __ldg(xr4 + i);
    }

    // ---- gather: float2 slots; thread owns slot tid (all 256) + slot 256+tid (tid<88) ----
    const float2* xin2 = (const float2*)xin;
    bool actB = tid < (RW2 - 256);   // tid < 88
    #pragma unroll
    for (int nl = 0; nl < GBN; nl++) {
        int n = node0 + nl;
        #pragma unroll
        for (int r = 0; r < NREL; r++) {
            int g  = r*NNODES + n;
            int s_ = dc_off[g], e_ = dc_off[g+1];
            float ax = 0.f, ay = 0.f, bx = 0.f, by = 0.f;
            int e = s_;
            for (; e + 2 <= e_; e += 2) {
                int s0 = __ldg(&dc_src[e])   * RW2;
                int s1 = __ldg(&dc_src[e+1]) * RW2;
                float2 v0 = __ldg(xin2 + s0 + tid);
                float2 v1 = __ldg(xin2 + s1 + tid);
                ax += v0.x + v1.x; ay += v0.y + v1.y;
                if (actB) {
                    float2 u0 = __ldg(xin2 + s0 + 256 + tid);
                    float2 u1 = __ldg(xin2 + s1 + 256 + tid);
                    bx += u0.x + u1.x; by += u0.y + u1.y;
                }
            }
            if (e < e_) {
                int s0 = __ldg(&dc_src[e]) * RW2;
                float2 v0 = __ldg(xin2 + s0 + tid);
                ax += v0.x; ay += v0.y;
                if (actB) {
                    float2 u0 = __ldg(xin2 + s0 + 256 + tid);
                    bx += u0.x; by += u0.y;
                }
            }
            float inv = dc_inv[g];
            float2* ab = (float2*)(agg_s + (r*GBN + nl)*RW);
            float2 wa; wa.x = ax*inv; wa.y = ay*inv;
            ab[tid] = wa;
            if (actB) { float2 wb2; wb2.x = bx*inv; wb2.y = by*inv; ab[256 + tid] = wb2; }
        }
    }
    __syncthreads();

    // ---- matmul: thread -> (part, nl, b); 8 parts of 6 outputs (o>=43 junk, never stored) ----
    int b    = tid & 15;
    int nl   = (tid >> 4) & 1;
    int part = tid >> 5;          // 0..7 (constant per warp => w_s reads broadcast)
    int n    = node0 + nl;
    int o0   = part * 6;

    float outv[6];
    #pragma unroll
    for (int oo = 0; oo < 6; oo++) outv[oo] = bias_s[o0 + oo];

    const float* xr = s_x + nl*RW + b*FEAT;
    for (int f = 0; f < FEAT; f++) {
        float xv = xr[f];
        const float* wr = w_s + f*FEAT + o0;
        #pragma unroll
        for (int oo = 0; oo < 6; oo++) outv[oo] += xv * wr[oo];
    }
    #pragma unroll
    for (int r = 0; r < NREL; r++) {
        const float* ar = agg_s + (r*GBN + nl)*RW + b*FEAT;
        const float* wb = w_s + (1 + r)*1849 + o0;
        for (int f = 0; f < FEAT; f++) {
            float av = ar[f];
            const float* wr = wb + f*FEAT;
            #pragma unroll
            for (int oo = 0; oo < 6; oo++) outv[oo] += av * wr[oo];
        }
    }

    float* yo = xout + (size_t)n*RW + b*FEAT;
    #pragma unroll
    for (int oo = 0; oo < 6; oo++) {
        int o = o0 + oo;
        if (o < FEAT) {
            float v = outv[oo];
            yo[o] = v > 0.f ? v : 0.01f*v;     // leaky_relu 0.01
        }
    }
}

// ---------------- head ([n][b][f] layout) ----------------
__global__ void k_head(const float* __restrict__ la, const int* __restrict__ sel,
                       const float* __restrict__ wf, const float* __restrict__ bf,
                       float* __restrict__ out)
{
    __shared__ float sh[501];
    __shared__ float rbuf[16];
    int b = blockIdx.x, t = threadIdx.x;
    if (t == 0) sh[0] = 0.f;                 // cash logit
    if (t < 500) {
        int node = __ldg(&sel[t]);
        float v = __ldg(bf) + __ldg(wf)*__ldg(&la[b*501 + 1 + t]);
        const float* xr = d_x  + (size_t)node*RW + b*FEAT;
        const float* hr = d_h2 + (size_t)node*RW + b*FEAT;
        #pragma unroll
        for (int f = 0; f < FEAT; f++) v += __ldg(&wf[1 + f])  * __ldg(xr + f);
        #pragma unroll
        for (int f = 0; f < FEAT; f++) v += __ldg(&wf[44 + f]) * __ldg(hr + f);
        sh[1 + t] = v;
    }
    __syncthreads();

    float m = -1e30f;
    for (int i = t; i < 501; i += 512) m = fmaxf(m, sh[i]);
    #pragma unroll
    for (int off = 16; off; off >>= 1) m = fmaxf(m, __shfl_xor_sync(0xffffffffu, m, off));
    if ((t & 31) == 0) rbuf[t >> 5] = m;
    __syncthreads();
    if (t == 0) { float mm = rbuf[0]; for (int w = 1; w < 16; w++) mm = fmaxf(mm, rbuf[w]); rbuf[0] = mm; }
    __syncthreads();
    float gm = rbuf[0];
    __syncthreads();

    float ssum = 0.f;
    for (int i = t; i < 501; i += 512) { float e = __expf(sh[i] - gm); sh[i] = e; ssum += e; }
    #pragma unroll
    for (int off = 16; off; off >>= 1) ssum += __shfl_xor_sync(0xffffffffu, ssum, off);
    if ((t & 31) == 0) rbuf[t >> 5] = ssum;
    __syncthreads();
    if (t == 0) { float s2 = 0.f; for (int w = 0; w < 16; w++) s2 += rbuf[w]; rbuf[0] = s2; }
    __syncthreads();
    float invs = 1.0f / rbuf[0];
    for (int i = t; i < 501; i += 512) out[b*501 + i] = sh[i] * invs;
}

// ---------------- launch ----------------
extern "C" void kernel_launch(void* const* d_in, const int* in_sizes, int n_in,
                              void* d_out, int out_size)
{
    const float* obs   = (const float*)d_in[0];
    const float* la    = (const float*)d_in[1];
    const int*   ei    = (const int*)  d_in[2];
    const int*   et    = (const int*)  d_in[3];
    const int*   sel   = (const int*)  d_in[4];
    const float* ws1   = (const float*)d_in[5];
    const float* bs1   = (const float*)d_in[6];
    const float* ws2   = (const float*)d_in[7];
    const float* bs2   = (const float*)d_in[8];
    const float* wm1   = (const float*)d_in[9];
    const float* bm1   = (const float*)d_in[10];
    const float* wm2   = (const float*)d_in[11];
    const float* bm2   = (const float*)d_in[12];
    const float* root1 = (const float*)d_in[13];
    const float* rel1  = (const float*)d_in[14];
    const float* bias1 = (const float*)d_in[15];
    const float* root2 = (const float*)d_in[16];
    const float* rel2  = (const float*)d_in[17];
    const float* bias2 = (const float*)d_in[18];
    const float* wf    = (const float*)d_in[19];
    const float* bf    = (const float*)d_in[20];
    float* out = (float*)d_out;

    int E = in_sizes[3];   // 96000

    int smem_t = (7504 + 150*OBSTR) * (int)sizeof(float);                      // 107416 B
    int smem_r = (7444 + GBN*RW + NREL*GBN*RW) * (int)sizeof(float);           // 51792 B -> 4 CTAs/SM
    cudaFuncSetAttribute(k_temporal, cudaFuncAttributeMaxDynamicSharedMemorySize, smem_t);
    cudaFuncSetAttribute(k_rgcn,     cudaFuncAttributeMaxDynamicSharedMemorySize, smem_r);

    // #0 count (dc_cnt zeroed by previous scan; BSS-zero on first call)
    k_count<<<(E + 255)/256, 256>>>(ei, et, E);
    // #1 scan (+ self-zero dc_cnt)
    k_scan<<<1, 1024>>>(E);
    // #2 fill
    k_fill<<<(E + 127)/128, 128>>>(ei, et, E);
    // #3 temporal   (ncu captures launch #3)
    k_temporal<<<ROWS/128, 384, smem_t>>>(obs, ws1, bs1, ws2, bs2, wm1, bm1, wm2, bm2);
    // #4, #5 RGCN layers
    k_rgcn<<<NNODES/GBN, 256, smem_r>>>(0, root1, rel1, bias1);
    k_rgcn<<<NNODES/GBN, 256, smem_r>>>(1, root2, rel2, bias2);
    // #6 head
    k_head<<<BATCH, 512>>>(la, sel, wf, bf, out);
}